// round 4
// baseline (speedup 1.0000x reference)
#include <cuda_runtime.h>

// Derivation: layer_norm over the size-1 kv feature axis returns exactly
// ln_k_b (mu=x, var=0), so k and v are identical for every key position;
// softmax over identical scores is uniform; o = mean_l(v) = v for every query.
// Hence out = msa + row, where row[c] = sum_d (ln_k_b*Wv[d] + bv[d])*Wo[d,c] + bo[c],
// broadcast over all 16384 rows. Exact identity, independent of input values.

__device__ float    g_row[256];
__device__ unsigned g_ready;   // zero-initialized; reset at end of every launch
__device__ unsigned g_done;    // zero-initialized; reset at end of every launch

__global__ void __launch_bounds__(256)
fused_kernel(const float4* __restrict__ msa4,
             float4* __restrict__ out4,
             const float* __restrict__ ln_k_b,
             const float* __restrict__ Wv,    // [1,256]
             const float* __restrict__ bv,    // [256]
             const float* __restrict__ Wo,    // [256,256]
             const float* __restrict__ bo,    // [256]
             int n4)
{
    const int t = threadIdx.x;
    const int b = blockIdx.x;

    // ---- 1. Issue the streaming loads FIRST (independent of the row) ----
    const int base = b * (256 * 4) + t;
    float4 m0, m1, m2, m3;
    const bool full = (base + 3 * 256) < n4;
    if (full) {
        m0 = msa4[base];
        m1 = msa4[base + 256];
        m2 = msa4[base + 512];
        m3 = msa4[base + 768];
    } else {
        m0 = m1 = m2 = m3 = make_float4(0.f, 0.f, 0.f, 0.f);
        if (base           < n4) m0 = msa4[base];
        if (base + 256     < n4) m1 = msa4[base + 256];
        if (base + 512     < n4) m2 = msa4[base + 512];
        if (base + 768     < n4) m3 = msa4[base + 768];
    }

    // ---- 2. Blocks 0..63 compute row[4b .. 4b+4) under the load latency ----
    if (b < 64) {
        __shared__ float4 part[256];
        float kb = ln_k_b[0];
        float vd = fmaf(kb, Wv[t], bv[t]);          // v[d=t]; kv_x == ln_k_b exactly
        float4 w = reinterpret_cast<const float4*>(Wo)[t * 64 + b];
        float4 p;
        p.x = vd * w.x; p.y = vd * w.y; p.z = vd * w.z; p.w = vd * w.w;
        part[t] = p;
        __syncthreads();
        #pragma unroll
        for (int s = 128; s >= 1; s >>= 1) {
            if (t < s) {
                float4 a = part[t], c = part[t + s];
                a.x += c.x; a.y += c.y; a.z += c.z; a.w += c.w;
                part[t] = a;
            }
            __syncthreads();
        }
        if (t == 0) {
            float4 r = part[0];
            float4 b4 = reinterpret_cast<const float4*>(bo)[b];
            r.x += b4.x; r.y += b4.y; r.z += b4.z; r.w += b4.w;
            reinterpret_cast<float4*>(g_row)[b] = r;
            __threadfence();                         // publish g_row before count
            atomicAdd(&g_ready, 1u);
        }
    }

    // ---- 3. Wait for the row to be complete (all 64 contributor blocks) ----
    if (t == 0) {
        volatile unsigned* vr = &g_ready;
        while (*vr < 64u) { }
        __threadfence();                             // acquire
    }
    __syncthreads();

    // ---- 4. Add broadcast row and store ----
    // (element index) mod 64 == t mod 64 for all 4 elements (stride 256 float4)
    float4 r = reinterpret_cast<const float4*>(g_row)[t & 63];
    m0.x += r.x; m0.y += r.y; m0.z += r.z; m0.w += r.w;
    m1.x += r.x; m1.y += r.y; m1.z += r.z; m1.w += r.w;
    m2.x += r.x; m2.y += r.y; m2.z += r.z; m2.w += r.w;
    m3.x += r.x; m3.y += r.y; m3.z += r.z; m3.w += r.w;
    if (full) {
        out4[base]       = m0;
        out4[base + 256] = m1;
        out4[base + 512] = m2;
        out4[base + 768] = m3;
    } else {
        if (base           < n4) out4[base]       = m0;
        if (base + 256     < n4) out4[base + 256] = m1;
        if (base + 512     < n4) out4[base + 512] = m2;
        if (base + 768     < n4) out4[base + 768] = m3;
    }

    // ---- 5. Self-reset so every launch starts from identical state ----
    __syncthreads();
    if (t == 0) {
        unsigned d = atomicAdd(&g_done, 1u);
        if (d == gridDim.x - 1u) {                   // last block to finish
            g_ready = 0u;
            g_done  = 0u;
            __threadfence();
        }
    }
}

extern "C" void kernel_launch(void* const* d_in, const int* in_sizes, int n_in,
                              void* d_out, int out_size)
{
    // metadata order: 0 msa, 1 saxs, 2 ln_q_w, 3 ln_q_b, 4 ln_k_w, 5 ln_k_b,
    //                 6 Wq, 7 bq, 8 Wk, 9 bk, 10 Wv, 11 bv, 12 Wo, 13 bo
    const float* msa    = (const float*)d_in[0];
    const float* ln_k_b = (const float*)d_in[5];
    const float* Wv     = (const float*)d_in[10];
    const float* bv     = (const float*)d_in[11];
    const float* Wo     = (const float*)d_in[12];
    const float* bo     = (const float*)d_in[13];
    float* out = (float*)d_out;

    int n4 = out_size / 4;                    // 1,048,576 float4
    int blocks = (n4 + 1023) / 1024;          // 1024 blocks, 4 float4/thread
    // Need >= 64 blocks so every row contributor exists (n4 >= 64K holds here).
    fused_kernel<<<blocks, 256>>>((const float4*)msa, (float4*)out,
                                  ln_k_b, Wv, bv, Wo, bo, n4);
}

// round 5
// speedup vs baseline: 1.2069x; 1.2069x over previous
#include <cuda_runtime.h>

// Derivation: layer_norm over the size-1 kv feature axis returns exactly
// ln_k_b (mu=x, var=0), so k and v are identical for every key position;
// softmax over identical scores is uniform; o = mean_l(v) = v for every query.
// Hence out = msa + row, row[c] = sum_d (ln_k_b*Wv[d] + bv[d])*Wo[d,c] + bo[c],
// broadcast over all 16384 rows. Exact identity, independent of input values.
__device__ float g_row[256];

// Kernel 1: 64 blocks x 256 threads. Block b computes row[4b..4b+4).
__global__ void compute_row_kernel(const float* __restrict__ ln_k_b,
                                   const float* __restrict__ Wv,   // [1,256]
                                   const float* __restrict__ bv,   // [256]
                                   const float* __restrict__ Wo,   // [256,256]
                                   const float* __restrict__ bo)   // [256]
{
    __shared__ float4 part[256];
    int t = threadIdx.x;
    int c4 = blockIdx.x;               // channels 4*c4 .. 4*c4+3
    float kb = ln_k_b[0];
    float vd = fmaf(kb, Wv[t], bv[t]); // v[d=t]; kv_x == ln_k_b exactly

    float4 w = reinterpret_cast<const float4*>(Wo)[t * 64 + c4];
    float4 p;
    p.x = vd * w.x; p.y = vd * w.y; p.z = vd * w.z; p.w = vd * w.w;
    part[t] = p;
    __syncthreads();

    #pragma unroll
    for (int s = 128; s >= 1; s >>= 1) {
        if (t < s) {
            float4 a = part[t], b = part[t + s];
            a.x += b.x; a.y += b.y; a.z += b.z; a.w += b.w;
            part[t] = a;
        }
        __syncthreads();
    }
    if (t == 0) {
        float4 r = part[0];
        float4 b4 = reinterpret_cast<const float4*>(bo)[c4];
        r.x += b4.x; r.y += b4.y; r.z += b4.z; r.w += b4.w;
        reinterpret_cast<float4*>(g_row)[c4] = r;
    }
}

// Kernel 2: out = msa + broadcast(row).
// 512 blocks x 256 threads x 8 float4/thread; 512*256*8 = 1,048,576 = n4
// exactly, so no bounds checks. All 8 loads issued back-to-back (MLP_p1=8).
__global__ void __launch_bounds__(256)
add_row_kernel(const float4* __restrict__ msa4,
               float4* __restrict__ out4)
{
    const int t = threadIdx.x;
    const int base = blockIdx.x * (256 * 8) + t;

    float4 m0 = msa4[base];
    float4 m1 = msa4[base + 256];
    float4 m2 = msa4[base + 512];
    float4 m3 = msa4[base + 768];
    float4 m4 = msa4[base + 1024];
    float4 m5 = msa4[base + 1280];
    float4 m6 = msa4[base + 1536];
    float4 m7 = msa4[base + 1792];

    // (element index) mod 64 == t mod 64 for all 8 elements (stride 256)
    float4 r = reinterpret_cast<const float4*>(g_row)[t & 63];

    m0.x += r.x; m0.y += r.y; m0.z += r.z; m0.w += r.w;
    m1.x += r.x; m1.y += r.y; m1.z += r.z; m1.w += r.w;
    m2.x += r.x; m2.y += r.y; m2.z += r.z; m2.w += r.w;
    m3.x += r.x; m3.y += r.y; m3.z += r.z; m3.w += r.w;
    m4.x += r.x; m4.y += r.y; m4.z += r.z; m4.w += r.w;
    m5.x += r.x; m5.y += r.y; m5.z += r.z; m5.w += r.w;
    m6.x += r.x; m6.y += r.y; m6.z += r.z; m6.w += r.w;
    m7.x += r.x; m7.y += r.y; m7.z += r.z; m7.w += r.w;

    out4[base]        = m0;
    out4[base + 256]  = m1;
    out4[base + 512]  = m2;
    out4[base + 768]  = m3;
    out4[base + 1024] = m4;
    out4[base + 1280] = m5;
    out4[base + 1536] = m6;
    out4[base + 1792] = m7;
}

extern "C" void kernel_launch(void* const* d_in, const int* in_sizes, int n_in,
                              void* d_out, int out_size)
{
    // metadata order: 0 msa, 1 saxs, 2 ln_q_w, 3 ln_q_b, 4 ln_k_w, 5 ln_k_b,
    //                 6 Wq, 7 bq, 8 Wk, 9 bk, 10 Wv, 11 bv, 12 Wo, 13 bo
    const float* msa    = (const float*)d_in[0];
    const float* ln_k_b = (const float*)d_in[5];
    const float* Wv     = (const float*)d_in[10];
    const float* bv     = (const float*)d_in[11];
    const float* Wo     = (const float*)d_in[12];
    const float* bo     = (const float*)d_in[13];
    float* out = (float*)d_out;

    compute_row_kernel<<<64, 256>>>(ln_k_b, Wv, bv, Wo, bo);

    // out_size = 4,194,304 floats -> n4 = 1,048,576 float4 = 512 * 2048
    add_row_kernel<<<512, 256>>>((const float4*)msa, (float4*)out);
}